// round 13
// baseline (speedup 1.0000x reference)
#include <cuda_runtime.h>
#include <cuda_fp16.h>
#include <cstdint>
#include <cstddef>

#define BB 16
#define MM 16
#define JXN 128
#define JQN 64
#define DN 256

// s_pm scratch: rowmax(s over q) + s_h, per global j row
__device__ float g_spm[BB * MM * JXN];

// ---------------- k1 smem layout (byte offsets), 98816 B per CTA -------------
constexpr int OFF_UH  = 0;        // half [64 q][264 d]   (B of GEMM1)     33792
constexpr int OFF_UH2 = 33792;    // u32  [32 qp][264 d]  (B of GEMM2)     33792
constexpr int OFF_AS  = 67584;    // half 2 x [64 j][72 d] A chunks (18432)
                                  //   ALIASED later by fp32 C1 [64][68] (17408)
constexpr int OFF_PH  = 86016;    // half [64 j][72 q]    (P = A of GEMM2)  9216
constexpr int OFF_W   = 95232;    // fp32 w1|w2|w3 (3072)
constexpr int OFF_SU  = 98304;    // fp32 s_u[64]
constexpr int OFF_SH  = 98560;    // fp32 s_h[64]
constexpr int SMEM_K1 = 98816;

#define MMA_F16(c, a, b)                                                        \
    asm volatile(                                                               \
        "mma.sync.aligned.m16n8k16.row.col.f32.f16.f16.f32 "                    \
        "{%0,%1,%2,%3}, {%4,%5,%6,%7}, {%8,%9}, {%0,%1,%2,%3};"                 \
        : "+f"((c)[0]), "+f"((c)[1]), "+f"((c)[2]), "+f"((c)[3])                \
        : "r"((a)[0]), "r"((a)[1]), "r"((a)[2]), "r"((a)[3]),                   \
          "r"((b)[0]), "r"((b)[1]))

__device__ __forceinline__ uint32_t pack_h2(float a, float b) {
    __half2 h = __floats2half2_rn(a, b);
    return *(uint32_t*)&h;
}
#define NBAR(id, cnt) asm volatile("bar.sync %0, %1;" :: "r"(id), "r"(cnt) : "memory")

// ---------------------------------------------------------------------------
// k1: CTA = one (b,m) x one 64-row j-half. 256 threads, 2 CTAs/SM.
// GEMM1 + q-softmax + GEMM2 + segments 0,1,2 + s_pm scratch.
// ---------------------------------------------------------------------------
__global__ void __launch_bounds__(256, 2)
attn_k1(const float* __restrict__ hg, const float* __restrict__ ug,
        const float* __restrict__ wg, float* __restrict__ out)
{
    extern __shared__ __align__(16) char smc[];
    __half*   u_h  = (__half*)(smc + OFF_UH);
    uint32_t* u_h2 = (uint32_t*)(smc + OFF_UH2);
    float*    sp   = (float*)(smc + OFF_AS);    // C1, aliases dead A_s
    __half*   P_h  = (__half*)(smc + OFF_PH);
    float*    wsm  = (float*)(smc + OFF_W);
    float*    s_u  = (float*)(smc + OFF_SU);
    float*    s_h  = (float*)(smc + OFF_SH);

    const int tid  = threadIdx.x;
    const int wid  = tid >> 5;
    const int lane = tid & 31;
    const int g    = lane >> 2;
    const int t    = lane & 3;
    const int bm   = blockIdx.x >> 1;
    const int half = blockIdx.x & 1;
    const int b    = bm >> 4;

    const float* __restrict__ hrow = hg + ((size_t)bm * JXN + half * 64) * DN;
    const float* __restrict__ ub   = ug + (size_t)b * JQN * DN;
    const size_t outbase = ((size_t)bm * JXN + half * 64) * (4 * DN);

    const int wj = wid & 1;                              // j-tile group (2 x 32)
    const int wn = wid >> 1;                             // n-tile group (4 x 16)
    const int srow = tid >> 2, soff = (tid & 3) * 16;

    // ---- early prefetch of GEMM1 chunk 0 ----
    float4 ph[4];
    #pragma unroll
    for (int i = 0; i < 4; i++)
        ph[i] = *(const float4*)(hrow + srow * DN + soff + 4 * i);

    // ---- stage w; u_h [q][264]; u_h2 [q-pair][264] (all conflict-free) ----
    for (int i = tid; i < 3 * DN; i += 256) wsm[i] = wg[i];
    for (int idx = tid; idx < 64 * 64; idx += 256) {
        int q = idx >> 6, d4 = idx & 63;
        float4 v = *(const float4*)(ub + q * DN + d4 * 4);
        *(uint2*)((char*)u_h + q * 528 + d4 * 8) =
            make_uint2(pack_h2(v.x, v.y), pack_h2(v.z, v.w));
    }
    for (int idx = tid; idx < 32 * 256; idx += 256) {
        int q2 = idx >> 8, d = idx & 255;
        float a = ub[(2 * q2) * DN + d];
        float c = ub[(2 * q2 + 1) * DN + d];
        u_h2[q2 * 264 + d] = pack_h2(a, c);
    }
    // ---- s_u[q] = u[q,:] . w2 ----
    {
        int q = tid >> 2, sg = tid & 3;
        const float* up  = ub + q * DN + sg * 64;
        const float* w2p = wg + DN + sg * 64;
        float acc = 0.f;
        #pragma unroll 16
        for (int i = 0; i < 16; i++) {
            float4 a = *(const float4*)(up + 4 * i);
            float4 w = *(const float4*)(w2p + 4 * i);
            acc += a.x * w.x + a.y * w.y + a.z * w.z + a.w * w.w;
        }
        acc += __shfl_xor_sync(0xffffffffu, acc, 1, 4);
        acc += __shfl_xor_sync(0xffffffffu, acc, 2, 4);
        if (sg == 0) s_u[q] = acc;
    }
    __syncthreads();

    // ---- GEMM1: C1[64 j][64 q] = (h*w3).u^T, K=256, 4 chunks, dbl-buffer ----
    float c1f[2][2][4];
    #pragma unroll
    for (int mt = 0; mt < 2; mt++)
        #pragma unroll
        for (int nt = 0; nt < 2; nt++)
            #pragma unroll
            for (int i = 0; i < 4; i++) c1f[mt][nt][i] = 0.f;

    float shp = 0.f;
    for (int c = 0; c < 4; c++) {
        __half* Ab = (__half*)(smc + OFF_AS + (c & 1) * 9216);
        {
            uint4 st0, st1;
            uint32_t* s0 = (uint32_t*)&st0;
            uint32_t* s1 = (uint32_t*)&st1;
            #pragma unroll
            for (int i = 0; i < 4; i++) {
                const int dd = c * 64 + soff + 4 * i;
                float4 x = ph[i];
                const float* w1p = wsm + dd;
                shp += x.x * w1p[0] + x.y * w1p[1] + x.z * w1p[2] + x.w * w1p[3];
                const float* w3p = wsm + 2 * DN + dd;
                uint32_t* dstp = (i < 2) ? (s0 + 2 * i) : (s1 + 2 * (i - 2));
                dstp[0] = pack_h2(x.x * w3p[0], x.y * w3p[1]);
                dstp[1] = pack_h2(x.z * w3p[2], x.w * w3p[3]);
            }
            *(uint4*)((char*)Ab + srow * 144 + soff * 2)      = st0;
            *(uint4*)((char*)Ab + srow * 144 + soff * 2 + 16) = st1;
        }
        __syncthreads();
        if (c < 3) {
            #pragma unroll
            for (int i = 0; i < 4; i++)
                ph[i] = *(const float4*)(hrow + srow * DN + (c + 1) * 64 + soff + 4 * i);
        }
        #pragma unroll
        for (int it = 0; it < 4; it++) {
            const int kb = it * 16;
            uint32_t af[2][4], bf[2][2];
            #pragma unroll
            for (int mt = 0; mt < 2; mt++) {
                const __half* ap = Ab + (wj * 32 + mt * 16 + g) * 72 + kb + 2 * t;
                af[mt][0] = *(const uint32_t*)ap;
                af[mt][1] = *(const uint32_t*)(ap + 8 * 72);
                af[mt][2] = *(const uint32_t*)(ap + 8);
                af[mt][3] = *(const uint32_t*)(ap + 8 * 72 + 8);
            }
            #pragma unroll
            for (int nt = 0; nt < 2; nt++) {
                const __half* bp = u_h + (wn * 16 + nt * 8 + g) * 264 + c * 64 + kb + 2 * t;
                bf[nt][0] = *(const uint32_t*)bp;
                bf[nt][1] = *(const uint32_t*)(bp + 8);
            }
            #pragma unroll
            for (int mt = 0; mt < 2; mt++)
                #pragma unroll
                for (int nt = 0; nt < 2; nt++)
                    MMA_F16(c1f[mt][nt], af[mt], bf[nt]);
        }
    }

    // ---- s_h ----
    shp += __shfl_xor_sync(0xffffffffu, shp, 1, 4);
    shp += __shfl_xor_sync(0xffffffffu, shp, 2, 4);
    if ((tid & 3) == 0) s_h[srow] = shp;
    __syncthreads();   // alias guard: all A_s MMA reads done before C1 store

    // ---- C1 fragments -> sp ----
    #pragma unroll
    for (int mt = 0; mt < 2; mt++)
        #pragma unroll
        for (int nt = 0; nt < 2; nt++) {
            float* cp = sp + (wj * 32 + mt * 16 + g) * 68 + wn * 16 + nt * 8 + 2 * t;
            *(float2*)cp            = make_float2(c1f[mt][nt][0], c1f[mt][nt][1]);
            *(float2*)(cp + 8 * 68) = make_float2(c1f[mt][nt][2], c1f[mt][nt][3]);
        }
    __syncthreads();

    // ---- softmax over q, warp-group aligned (warp: 8 rows of its wj group);
    //      writes P_h fp16 + s_pm straight to global scratch ----
    {
        const int r2 = 32 * wj + 8 * wn + (lane >> 2);
        const int o2 = (lane & 3) * 16;
        float v[16];
        #pragma unroll
        for (int i = 0; i < 16; i++) v[i] = sp[r2 * 68 + o2 + i] + s_u[o2 + i];
        float mx = v[0];
        #pragma unroll
        for (int i = 1; i < 16; i++) mx = fmaxf(mx, v[i]);
        mx = fmaxf(mx, __shfl_xor_sync(0xffffffffu, mx, 1, 4));
        mx = fmaxf(mx, __shfl_xor_sync(0xffffffffu, mx, 2, 4));
        float sum = 0.f;
        #pragma unroll
        for (int i = 0; i < 16; i++) { v[i] = __expf(v[i] - mx); sum += v[i]; }
        sum += __shfl_xor_sync(0xffffffffu, sum, 1, 4);
        sum += __shfl_xor_sync(0xffffffffu, sum, 2, 4);
        float inv = 1.f / sum;
        uint4 st0, st1;
        uint32_t* s0 = (uint32_t*)&st0;
        uint32_t* s1 = (uint32_t*)&st1;
        #pragma unroll
        for (int i = 0; i < 4; i++) {
            uint32_t* dstp = (i < 2) ? (s0 + 2 * i) : (s1 + 2 * (i - 2));
            dstp[0] = pack_h2(v[4 * i + 0] * inv, v[4 * i + 1] * inv);
            dstp[1] = pack_h2(v[4 * i + 2] * inv, v[4 * i + 3] * inv);
        }
        *(uint4*)((char*)P_h + r2 * 144 + o2 * 2)      = st0;
        *(uint4*)((char*)P_h + r2 * 144 + o2 * 2 + 16) = st1;
        if ((lane & 3) == 0)
            g_spm[bm * JXN + half * 64 + r2] = mx + s_h[r2];
    }
    // group barrier: 4 warps sharing wj exchange their P rows (ids 1..2, 128 thr)
    NBAR(1 + wj, 128);

    // ---- GEMM2 (barrier-free): u_att[rows 32wj..+31][256 d] = P . u ----
    float d2f[2][8][4];
    #pragma unroll
    for (int mt = 0; mt < 2; mt++)
        #pragma unroll
        for (int nt = 0; nt < 8; nt++)
            #pragma unroll
            for (int i = 0; i < 4; i++) d2f[mt][nt][i] = 0.f;

    #pragma unroll
    for (int it = 0; it < 4; it++) {
        const int kb = it * 16;
        uint32_t af[2][4];
        #pragma unroll
        for (int mt = 0; mt < 2; mt++) {
            const __half* ap = P_h + (wj * 32 + mt * 16 + g) * 72 + kb + 2 * t;
            af[mt][0] = *(const uint32_t*)ap;
            af[mt][1] = *(const uint32_t*)(ap + 8 * 72);
            af[mt][2] = *(const uint32_t*)(ap + 8);
            af[mt][3] = *(const uint32_t*)(ap + 8 * 72 + 8);
        }
        #pragma unroll
        for (int nt = 0; nt < 8; nt++) {
            const int dcol = wn * 64 + nt * 8 + g;
            uint32_t bf[2];
            bf[0] = u_h2[(it * 8 + t) * 264 + dcol];
            bf[1] = u_h2[(it * 8 + t + 4) * 264 + dcol];
            MMA_F16(d2f[0][nt], af[0], bf);
            MMA_F16(d2f[1][nt], af[1], bf);
        }
    }

    // ---- direct epilogue: segments 0,1,2 via STG.64 (quad = 32B sector) ----
    #pragma unroll
    for (int mt = 0; mt < 2; mt++) {
        const int R0 = wj * 32 + mt * 16 + g;
        const int R1 = R0 + 8;
        float* ob0 = out + outbase + (size_t)R0 * (4 * DN);
        float* ob1 = out + outbase + (size_t)R1 * (4 * DN);
        const float* h0 = hrow + R0 * DN;
        const float* h1 = hrow + R1 * DN;
        #pragma unroll
        for (int nt = 0; nt < 8; nt++) {
            const int d = wn * 64 + nt * 8 + 2 * t;
            float2 hv0 = *(const float2*)(h0 + d);
            float2 hv1 = *(const float2*)(h1 + d);
            float2 ua0 = make_float2(d2f[0][nt][0], d2f[0][nt][1]);
            float2 ua1 = make_float2(d2f[0][nt][2], d2f[0][nt][3]);
            if (mt == 1) {
                ua0 = make_float2(d2f[1][nt][0], d2f[1][nt][1]);
                ua1 = make_float2(d2f[1][nt][2], d2f[1][nt][3]);
            }
            *(float2*)(ob0 + d)          = hv0;                                   // seg 0
            *(float2*)(ob0 + DN + d)     = ua0;                                   // seg 1
            *(float2*)(ob0 + 2 * DN + d) = make_float2(hv0.x * ua0.x, hv0.y * ua0.y); // seg 2
            *(float2*)(ob1 + d)          = hv1;
            *(float2*)(ob1 + DN + d)     = ua1;
            *(float2*)(ob1 + 2 * DN + d) = make_float2(hv1.x * ua1.x, hv1.y * ua1.y);
        }
    }
}

// ---------------------------------------------------------------------------
// k2: CTA = one (b,m, d-half). p = softmax_j(g_spm); h_att = sum_j p_j h_j;
// writes segment 3 only.
// ---------------------------------------------------------------------------
__global__ void __launch_bounds__(256)
attn_k2(const float* __restrict__ hg, float* __restrict__ out)
{
    __shared__ float  p_s[JXN];
    __shared__ float4 part[8][32];

    const int bm  = blockIdx.x >> 1;
    const int dh  = (blockIdx.x & 1) * 128;
    const int tid = threadIdx.x;
    const float* __restrict__ hb = hg + (size_t)bm * JXN * DN;

    if (tid < 32) {
        float v0 = g_spm[bm * JXN + tid];
        float v1 = g_spm[bm * JXN + tid + 32];
        float v2 = g_spm[bm * JXN + tid + 64];
        float v3 = g_spm[bm * JXN + tid + 96];
        float mx = fmaxf(fmaxf(v0, v1), fmaxf(v2, v3));
        #pragma unroll
        for (int o = 16; o >= 1; o >>= 1) mx = fmaxf(mx, __shfl_xor_sync(0xffffffffu, mx, o));
        float e0 = __expf(v0 - mx), e1 = __expf(v1 - mx);
        float e2 = __expf(v2 - mx), e3 = __expf(v3 - mx);
        float s = e0 + e1 + e2 + e3;
        #pragma unroll
        for (int o = 16; o >= 1; o >>= 1) s += __shfl_xor_sync(0xffffffffu, s, o);
        float inv = 1.f / s;
        p_s[tid]      = e0 * inv;
        p_s[tid + 32] = e1 * inv;
        p_s[tid + 64] = e2 * inv;
        p_s[tid + 96] = e3 * inv;
    }
    __syncthreads();

    const int jg = tid >> 5, dq = tid & 31;
    const int dof = dh + dq * 4;

    float4 acc = make_float4(0.f, 0.f, 0.f, 0.f);
    #pragma unroll 4
    for (int j = jg * 16; j < jg * 16 + 16; j++) {
        float4 hv = *(const float4*)(hb + j * DN + dof);
        float pj = p_s[j];
        acc.x += pj * hv.x; acc.y += pj * hv.y; acc.z += pj * hv.z; acc.w += pj * hv.w;
    }
    part[jg][dq] = acc;
    __syncthreads();
    if (tid < 32) {
        float4 s = part[0][tid];
        #pragma unroll
        for (int g = 1; g < 8; g++) {
            float4 v = part[g][tid];
            s.x += v.x; s.y += v.y; s.z += v.z; s.w += v.w;
        }
        part[0][tid] = s;
    }
    __syncthreads();
    const float4 ha = part[0][dq];
    #pragma unroll 2
    for (int j = jg * 16; j < jg * 16 + 16; j++) {
        float4 hv = *(const float4*)(hb + j * DN + dof);   // L1-hot second read
        float4 o;
        o.x = hv.x * ha.x; o.y = hv.y * ha.y; o.z = hv.z * ha.z; o.w = hv.w * ha.w;
        *(float4*)(out + (size_t)(bm * JXN + j) * (4 * DN) + 3 * DN + dof) = o;
    }
}

// ---------------------------------------------------------------------------
extern "C" void kernel_launch(void* const* d_in, const int* in_sizes, int n_in,
                              void* d_out, int out_size)
{
    (void)in_sizes; (void)n_in; (void)out_size;
    const float* h = (const float*)d_in[0];
    const float* u = (const float*)d_in[1];
    const float* w = (const float*)d_in[2];
    // d_in[3] (scalar bias b) cancels in both softmaxes -> unused.
    float* out = (float*)d_out;

    cudaFuncSetAttribute(attn_k1, cudaFuncAttributeMaxDynamicSharedMemorySize, SMEM_K1);
    attn_k1<<<BB * MM * 2, 256, SMEM_K1>>>(h, u, w, out);
    attn_k2<<<BB * MM * 2, 256>>>(h, out);
}

// round 14
// speedup vs baseline: 1.1701x; 1.1701x over previous
#include <cuda_runtime.h>
#include <cuda_fp16.h>
#include <cstdint>
#include <cstddef>

#define BB 16
#define MM 16
#define JXN 128
#define JQN 64
#define DN 256

// ---------------- smem layout (byte offsets), 111360 B per CTA ---------------
constexpr int OFF_UH  = 0;        // half [64 q][264 d] (B of GEMM1)        33792
                                  //   ALIASED after GEMM1 by fp32 C1 [128][66]
constexpr int OFF_UH2 = 33792;    // u32  [32 qp][264 d] (B of GEMM2)       33792
constexpr int OFF_AS  = 67584;    // half 2 x [128 j][40 d] A chunks        20480
                                  //   ALIASED later by part float4[4][64]  (4096)
constexpr int OFF_PH  = 88064;    // half [128 j][72 q] (P = A of GEMM2)    18432
constexpr int OFF_W   = 106496;   // fp32 w1|w2|w3 (3072)
constexpr int OFF_SU  = 109568;   // fp32 s_u[64]
constexpr int OFF_SH  = 109824;   // fp32 s_h[128]
constexpr int OFF_SPM = 110336;   // fp32 s_pm[128]
constexpr int OFF_PS  = 110848;   // fp32 p_s[128]
constexpr int SMEM_BYTES = 111360;

#define MMA_F16(c, a, b)                                                        \
    asm volatile(                                                               \
        "mma.sync.aligned.m16n8k16.row.col.f32.f16.f16.f32 "                    \
        "{%0,%1,%2,%3}, {%4,%5,%6,%7}, {%8,%9}, {%0,%1,%2,%3};"                 \
        : "+f"((c)[0]), "+f"((c)[1]), "+f"((c)[2]), "+f"((c)[3])                \
        : "r"((a)[0]), "r"((a)[1]), "r"((a)[2]), "r"((a)[3]),                   \
          "r"((b)[0]), "r"((b)[1]))

__device__ __forceinline__ uint32_t pack_h2(float a, float b) {
    __half2 h = __floats2half2_rn(a, b);
    return *(uint32_t*)&h;
}

// ---------------------------------------------------------------------------
// Fused kernel: CTA = one (b,m), all 128 j rows. 256 threads, 2 CTAs/SM.
// ---------------------------------------------------------------------------
__global__ void __launch_bounds__(256, 2)
attn_h16(const float* __restrict__ hg, const float* __restrict__ ug,
         const float* __restrict__ wg, float* __restrict__ out)
{
    extern __shared__ __align__(16) char smc[];
    __half*   u_h  = (__half*)(smc + OFF_UH);
    float*    C1f  = (float*)(smc + OFF_UH);    // alias, live after GEMM1
    uint32_t* u_h2 = (uint32_t*)(smc + OFF_UH2);
    __half*   P_h  = (__half*)(smc + OFF_PH);
    float*    wsm  = (float*)(smc + OFF_W);
    float*    s_u  = (float*)(smc + OFF_SU);
    float*    s_h  = (float*)(smc + OFF_SH);
    float*    s_pm = (float*)(smc + OFF_SPM);
    float*    p_s  = (float*)(smc + OFF_PS);
    float4*   part = (float4*)(smc + OFF_AS);   // alias, live after GEMM2

    const int tid  = threadIdx.x;
    const int wid  = tid >> 5;
    const int lane = tid & 31;
    const int g    = lane >> 2;
    const int t    = lane & 3;
    const int bm   = blockIdx.x;
    const int b    = bm >> 4;

    const float* __restrict__ hrow = hg + (size_t)bm * JXN * DN;
    const float* __restrict__ ub   = ug + (size_t)b * JQN * DN;
    const size_t outbase = (size_t)bm * JXN * (4 * DN);

    const int wj = wid & 3;                          // j-tile group (4 x 32 rows)
    const int wn = wid >> 2;                         // q/d tile group (2)
    const int srow = tid >> 1, sh16 = (tid & 1) * 16; // staging: row, 16-d half

    // ---- early prefetch of GEMM1 chunk 0 (16 d per thread) ----
    float4 ph[4];
    #pragma unroll
    for (int i = 0; i < 4; i++)
        ph[i] = *(const float4*)(hrow + srow * DN + sh16 + 4 * i);

    // ---- stage w; u_h [q][264]; u_h2 [q-pair][264] ----
    for (int i = tid; i < 3 * DN; i += 256) wsm[i] = wg[i];
    for (int idx = tid; idx < 64 * 64; idx += 256) {
        int q = idx >> 6, d4 = idx & 63;
        float4 v = *(const float4*)(ub + q * DN + d4 * 4);
        *(uint2*)((char*)u_h + q * 528 + d4 * 8) =
            make_uint2(pack_h2(v.x, v.y), pack_h2(v.z, v.w));
    }
    for (int idx = tid; idx < 32 * 256; idx += 256) {
        int q2 = idx >> 8, d = idx & 255;
        float a = ub[(2 * q2) * DN + d];
        float c = ub[(2 * q2 + 1) * DN + d];
        u_h2[q2 * 264 + d] = pack_h2(a, c);
    }
    // ---- s_u[q] = u[q,:] . w2 (4 lanes per q) ----
    {
        int q = tid >> 2, sg = tid & 3;
        const float* up  = ub + q * DN + sg * 64;
        const float* w2p = wg + DN + sg * 64;
        float acc = 0.f;
        #pragma unroll 16
        for (int i = 0; i < 16; i++) {
            float4 a = *(const float4*)(up + 4 * i);
            float4 w = *(const float4*)(w2p + 4 * i);
            acc += a.x * w.x + a.y * w.y + a.z * w.z + a.w * w.w;
        }
        acc += __shfl_xor_sync(0xffffffffu, acc, 1, 4);
        acc += __shfl_xor_sync(0xffffffffu, acc, 2, 4);
        if (sg == 0) s_u[q] = acc;
    }
    __syncthreads();

    // ---- GEMM1: C1[128 j][64 q] = (h*w3).u^T, K=256, 8 chunks of 32, dbl-buf ----
    float c1f[2][4][4];
    #pragma unroll
    for (int mt = 0; mt < 2; mt++)
        #pragma unroll
        for (int nt = 0; nt < 4; nt++)
            #pragma unroll
            for (int i = 0; i < 4; i++) c1f[mt][nt][i] = 0.f;

    float shp = 0.f;
    for (int c = 0; c < 8; c++) {
        __half* Ab = (__half*)(smc + OFF_AS + (c & 1) * 10240);
        {
            uint4 st0, st1;
            uint32_t* s0 = (uint32_t*)&st0;
            uint32_t* s1 = (uint32_t*)&st1;
            #pragma unroll
            for (int i = 0; i < 4; i++) {
                const int dd = c * 32 + sh16 + 4 * i;
                float4 x = ph[i];
                const float* w1p = wsm + dd;
                shp += x.x * w1p[0] + x.y * w1p[1] + x.z * w1p[2] + x.w * w1p[3];
                const float* w3p = wsm + 2 * DN + dd;
                uint32_t* dstp = (i < 2) ? (s0 + 2 * i) : (s1 + 2 * (i - 2));
                dstp[0] = pack_h2(x.x * w3p[0], x.y * w3p[1]);
                dstp[1] = pack_h2(x.z * w3p[2], x.w * w3p[3]);
            }
            *(uint4*)((char*)Ab + srow * 80 + sh16 * 2)      = st0;
            *(uint4*)((char*)Ab + srow * 80 + sh16 * 2 + 16) = st1;
        }
        __syncthreads();
        if (c < 7) {
            #pragma unroll
            for (int i = 0; i < 4; i++)
                ph[i] = *(const float4*)(hrow + srow * DN + (c + 1) * 32 + sh16 + 4 * i);
        }
        #pragma unroll
        for (int it = 0; it < 2; it++) {
            const int kb = it * 16;
            uint32_t af[2][4], bf[4][2];
            #pragma unroll
            for (int mt = 0; mt < 2; mt++) {
                const __half* ap = Ab + (wj * 32 + mt * 16 + g) * 40 + kb + 2 * t;
                af[mt][0] = *(const uint32_t*)ap;
                af[mt][1] = *(const uint32_t*)(ap + 8 * 40);
                af[mt][2] = *(const uint32_t*)(ap + 8);
                af[mt][3] = *(const uint32_t*)(ap + 8 * 40 + 8);
            }
            #pragma unroll
            for (int nt = 0; nt < 4; nt++) {
                const __half* bp = u_h + (wn * 32 + nt * 8 + g) * 264 + c * 32 + kb + 2 * t;
                bf[nt][0] = *(const uint32_t*)bp;
                bf[nt][1] = *(const uint32_t*)(bp + 8);
            }
            #pragma unroll
            for (int mt = 0; mt < 2; mt++)
                #pragma unroll
                for (int nt = 0; nt < 4; nt++)
                    MMA_F16(c1f[mt][nt], af[mt], bf[nt]);
        }
        // no trailing sync: next STS targets the other A buffer
    }

    // ---- s_h ----
    shp += __shfl_xor_sync(0xffffffffu, shp, 1, 2);
    if ((tid & 1) == 0) s_h[srow] = shp;
    __syncthreads();   // all GEMM1 MMA reads of u_h done -> C1 alias safe

    // ---- C1 fragments -> C1f (stride 66) ----
    #pragma unroll
    for (int mt = 0; mt < 2; mt++)
        #pragma unroll
        for (int nt = 0; nt < 4; nt++) {
            float* cp = C1f + (wj * 32 + mt * 16 + g) * 66 + wn * 32 + nt * 8 + 2 * t;
            *(float2*)cp            = make_float2(c1f[mt][nt][0], c1f[mt][nt][1]);
            *(float2*)(cp + 8 * 66) = make_float2(c1f[mt][nt][2], c1f[mt][nt][3]);
        }
    __syncthreads();

    // ---- softmax over q (thread: one row, 32 q; pair-lane reduce) ----
    {
        const int row = 32 * wj + 16 * wn + (lane >> 1);
        const int o2  = (lane & 1) * 32;
        float v[32];
        #pragma unroll
        for (int i = 0; i < 32; i++) v[i] = C1f[row * 66 + o2 + i] + s_u[o2 + i];
        float mx = v[0];
        #pragma unroll
        for (int i = 1; i < 32; i++) mx = fmaxf(mx, v[i]);
        mx = fmaxf(mx, __shfl_xor_sync(0xffffffffu, mx, 1, 2));
        float sum = 0.f;
        #pragma unroll
        for (int i = 0; i < 32; i++) { v[i] = __expf(v[i] - mx); sum += v[i]; }
        sum += __shfl_xor_sync(0xffffffffu, sum, 1, 2);
        float inv = 1.f / sum;
        #pragma unroll
        for (int hfq = 0; hfq < 2; hfq++) {
            uint4 st;
            uint32_t* sw = (uint32_t*)&st;
            #pragma unroll
            for (int i = 0; i < 4; i++) {
                int base = hfq * 16 + 4 * i;
                sw[i] = 0;  // placeholder overwritten below
            }
            sw[0] = pack_h2(v[hfq*16+0]*inv,  v[hfq*16+1]*inv);
            sw[1] = pack_h2(v[hfq*16+2]*inv,  v[hfq*16+3]*inv);
            sw[2] = pack_h2(v[hfq*16+4]*inv,  v[hfq*16+5]*inv);
            sw[3] = pack_h2(v[hfq*16+6]*inv,  v[hfq*16+7]*inv);
            *(uint4*)((char*)P_h + row * 144 + o2 * 2 + hfq * 32) = st;
            uint4 st2;
            uint32_t* sw2 = (uint32_t*)&st2;
            sw2[0] = pack_h2(v[hfq*16+8]*inv,  v[hfq*16+9]*inv);
            sw2[1] = pack_h2(v[hfq*16+10]*inv, v[hfq*16+11]*inv);
            sw2[2] = pack_h2(v[hfq*16+12]*inv, v[hfq*16+13]*inv);
            sw2[3] = pack_h2(v[hfq*16+14]*inv, v[hfq*16+15]*inv);
            *(uint4*)((char*)P_h + row * 144 + o2 * 2 + hfq * 32 + 16) = st2;
        }
        if ((lane & 1) == 0) s_pm[row] = mx + s_h[row];
    }
    __syncthreads();   // all P_h + s_pm visible

    // ---- p = softmax_j(s_pm) (warp 0; overlaps other warps' GEMM2 start) ----
    if (wid == 0) {
        float v0 = s_pm[lane], v1 = s_pm[lane + 32], v2 = s_pm[lane + 64], v3 = s_pm[lane + 96];
        float mx = fmaxf(fmaxf(v0, v1), fmaxf(v2, v3));
        #pragma unroll
        for (int o = 16; o >= 1; o >>= 1) mx = fmaxf(mx, __shfl_xor_sync(0xffffffffu, mx, o));
        float e0 = __expf(v0 - mx), e1 = __expf(v1 - mx);
        float e2 = __expf(v2 - mx), e3 = __expf(v3 - mx);
        float s = e0 + e1 + e2 + e3;
        #pragma unroll
        for (int o = 16; o >= 1; o >>= 1) s += __shfl_xor_sync(0xffffffffu, s, o);
        float inv = 1.f / s;
        p_s[lane] = e0 * inv; p_s[lane + 32] = e1 * inv;
        p_s[lane + 64] = e2 * inv; p_s[lane + 96] = e3 * inv;
    }

    // ---- GEMM2 (barrier-free): 2 d-slabs of 128; direct epilogue segs 0,1,2 ----
    for (int s = 0; s < 2; s++) {
        float d2f[2][8][4];
        #pragma unroll
        for (int mt = 0; mt < 2; mt++)
            #pragma unroll
            for (int nt = 0; nt < 8; nt++)
                #pragma unroll
                for (int i = 0; i < 4; i++) d2f[mt][nt][i] = 0.f;

        #pragma unroll
        for (int it = 0; it < 4; it++) {
            const int kb = it * 16;
            uint32_t af[2][4];
            #pragma unroll
            for (int mt = 0; mt < 2; mt++) {
                const __half* ap = P_h + (wj * 32 + mt * 16 + g) * 72 + kb + 2 * t;
                af[mt][0] = *(const uint32_t*)ap;
                af[mt][1] = *(const uint32_t*)(ap + 8 * 72);
                af[mt][2] = *(const uint32_t*)(ap + 8);
                af[mt][3] = *(const uint32_t*)(ap + 8 * 72 + 8);
            }
            #pragma unroll
            for (int nt = 0; nt < 8; nt++) {
                const int dcol = s * 128 + wn * 64 + nt * 8 + g;
                uint32_t bf[2];
                bf[0] = u_h2[(it * 8 + t) * 264 + dcol];
                bf[1] = u_h2[(it * 8 + t + 4) * 264 + dcol];
                MMA_F16(d2f[0][nt], af[0], bf);
                MMA_F16(d2f[1][nt], af[1], bf);
            }
        }
        #pragma unroll
        for (int mt = 0; mt < 2; mt++) {
            const int R0 = wj * 32 + mt * 16 + g;
            const int R1 = R0 + 8;
            float* ob0 = out + outbase + (size_t)R0 * (4 * DN);
            float* ob1 = out + outbase + (size_t)R1 * (4 * DN);
            const float* h0 = hrow + R0 * DN;
            const float* h1 = hrow + R1 * DN;
            #pragma unroll
            for (int nt = 0; nt < 8; nt++) {
                const int d = s * 128 + wn * 64 + nt * 8 + 2 * t;
                float2 hv0 = *(const float2*)(h0 + d);
                float2 hv1 = *(const float2*)(h1 + d);
                float2 ua0 = make_float2(d2f[mt][nt][0], d2f[mt][nt][1]);
                float2 ua1 = make_float2(d2f[mt][nt][2], d2f[mt][nt][3]);
                *(float2*)(ob0 + d)          = hv0;                                    // seg 0
                *(float2*)(ob0 + DN + d)     = ua0;                                    // seg 1
                *(float2*)(ob0 + 2 * DN + d) = make_float2(hv0.x * ua0.x, hv0.y * ua0.y); // seg 2
                *(float2*)(ob1 + d)          = hv1;
                *(float2*)(ob1 + DN + d)     = ua1;
                *(float2*)(ob1 + 2 * DN + d) = make_float2(hv1.x * ua1.x, hv1.y * ua1.y);
            }
        }
    }
    __syncthreads();   // p_s visible to all; A_s region free for part alias

    // ---- h_att = sum_j p_j h[j,:]; write segment 3 ----
    {
        const int jg = tid >> 6, dq = tid & 63;   // 4 groups x 32 j; 64 float4 d
        float4 acc = make_float4(0.f, 0.f, 0.f, 0.f);
        #pragma unroll 4
        for (int j = jg * 32; j < jg * 32 + 32; j++) {
            float4 hv = *(const float4*)(hrow + j * DN + dq * 4);
            float pj = p_s[j];
            acc.x += pj * hv.x; acc.y += pj * hv.y; acc.z += pj * hv.z; acc.w += pj * hv.w;
        }
        part[jg * 64 + dq] = acc;
        __syncthreads();
        if (tid < 64) {
            float4 sacc = part[tid];
            #pragma unroll
            for (int gg = 1; gg < 4; gg++) {
                float4 v = part[gg * 64 + tid];
                sacc.x += v.x; sacc.y += v.y; sacc.z += v.z; sacc.w += v.w;
            }
            part[tid] = sacc;
        }
        __syncthreads();
        const float4 ha = part[dq];
        #pragma unroll 4
        for (int j = jg * 32; j < jg * 32 + 32; j++) {
            float4 hv = *(const float4*)(hrow + j * DN + dq * 4);   // L1/L2-hot
            float4 o3;
            o3.x = hv.x * ha.x; o3.y = hv.y * ha.y; o3.z = hv.z * ha.z; o3.w = hv.w * ha.w;
            *(float4*)(out + outbase + (size_t)j * (4 * DN) + 3 * DN + dq * 4) = o3;
        }
    }
}

// ---------------------------------------------------------------------------
extern "C" void kernel_launch(void* const* d_in, const int* in_sizes, int n_in,
                              void* d_out, int out_size)
{
    (void)in_sizes; (void)n_in; (void)out_size;
    const float* h = (const float*)d_in[0];
    const float* u = (const float*)d_in[1];
    const float* w = (const float*)d_in[2];
    // d_in[3] (scalar bias b) cancels in both softmaxes -> unused.
    float* out = (float*)d_out;

    cudaFuncSetAttribute(attn_h16, cudaFuncAttributeMaxDynamicSharedMemorySize, SMEM_BYTES);
    attn_h16<<<BB * MM, 256, SMEM_BYTES>>>(h, u, w, out);
}

// round 15
// speedup vs baseline: 1.3224x; 1.1301x over previous
#include <cuda_runtime.h>
#include <cuda_fp16.h>
#include <cstdint>
#include <cstddef>

#define BB 16
#define MM 16
#define JXN 128
#define JQN 64
#define DN 256

// ---------------- smem layout (byte offsets), 78592 B per CTA ----------------
constexpr int OFF_UH  = 0;        // half [64 q][264 d] (B of GEMM1 + GEMM2) 33792
constexpr int OFF_AS  = 33792;    // half 2 x [128 j][40 d] A chunks         20480
                                  //   ALIASED post-GEMM2 by part float4[4][64]
constexpr int OFF_PH  = 54272;    // half [128 j][72 q] (P = A of GEMM2)     18432
constexpr int OFF_W   = 72704;    // fp32 w1|w2|w3 (3072)
constexpr int OFF_SU  = 75776;    // fp32 s_u[64]
constexpr int OFF_SH  = 76032;    // fp32 s_h[128]
constexpr int OFF_SPM = 76544;    // fp32 s_pm[128] (rowmax only)
constexpr int OFF_PS  = 77056;    // fp32 p_s[128]
constexpr int OFF_EX  = 77568;    // fp32 exch[2][128] (softmax cross-warp)
constexpr int SMEM_BYTES = 78592;

#define MMA_F16(c, a, b)                                                        \
    asm volatile(                                                               \
        "mma.sync.aligned.m16n8k16.row.col.f32.f16.f16.f32 "                    \
        "{%0,%1,%2,%3}, {%4,%5,%6,%7}, {%8,%9}, {%0,%1,%2,%3};"                 \
        : "+f"((c)[0]), "+f"((c)[1]), "+f"((c)[2]), "+f"((c)[3])                \
        : "r"((a)[0]), "r"((a)[1]), "r"((a)[2]), "r"((a)[3]),                   \
          "r"((b)[0]), "r"((b)[1]))

#define LDMATRIX_X4_TRANS(r0, r1, r2, r3, addr)                                 \
    asm volatile(                                                               \
        "ldmatrix.sync.aligned.m8n8.x4.trans.shared.b16 {%0,%1,%2,%3}, [%4];"   \
        : "=r"(r0), "=r"(r1), "=r"(r2), "=r"(r3) : "r"(addr))

__device__ __forceinline__ uint32_t pack_h2(float a, float b) {
    __half2 h = __floats2half2_rn(a, b);
    return *(uint32_t*)&h;
}
__device__ __forceinline__ uint32_t smem_u32(const void* p) {
    uint32_t a;
    asm("{ .reg .u64 t; cvta.to.shared.u64 t, %1; cvt.u32.u64 %0, t; }" : "=r"(a) : "l"(p));
    return a;
}
#define NBAR(id, cnt)  asm volatile("bar.sync %0, %1;"   :: "r"(id), "r"(cnt) : "memory")
#define NBARR(id, cnt) asm volatile("bar.arrive %0, %1;" :: "r"(id), "r"(cnt) : "memory")

// ---------------------------------------------------------------------------
// Fused kernel: CTA = one (b,m), all 128 j rows. 256 threads, 2 CTAs/SM.
// ---------------------------------------------------------------------------
__global__ void __launch_bounds__(256, 2)
attn_h16(const float* __restrict__ hg, const float* __restrict__ ug,
         const float* __restrict__ wg, float* __restrict__ out)
{
    extern __shared__ __align__(16) char smc[];
    __half*   u_h  = (__half*)(smc + OFF_UH);
    __half*   P_h  = (__half*)(smc + OFF_PH);
    float*    wsm  = (float*)(smc + OFF_W);
    float*    s_u  = (float*)(smc + OFF_SU);
    float*    s_h  = (float*)(smc + OFF_SH);
    float*    s_pm = (float*)(smc + OFF_SPM);
    float*    p_s  = (float*)(smc + OFF_PS);
    float*    exch = (float*)(smc + OFF_EX);
    float4*   part = (float4*)(smc + OFF_AS);   // alias, live after GEMM2

    const int tid  = threadIdx.x;
    const int wid  = tid >> 5;
    const int lane = tid & 31;
    const int g    = lane >> 2;
    const int t    = lane & 3;
    const int bm   = blockIdx.x;
    const int b    = bm >> 4;

    const float* __restrict__ hrow = hg + (size_t)bm * JXN * DN;
    const float* __restrict__ ub   = ug + (size_t)b * JQN * DN;
    const size_t outbase = (size_t)bm * JXN * (4 * DN);

    const int wj = wid & 3;                           // j-tile group (4 x 32 rows)
    const int wn = wid >> 2;                          // q/d tile group (2)
    const int srow = tid >> 1, sh16 = (tid & 1) * 16; // staging: row, 16-d half

    // ---- early prefetch of GEMM1 chunk 0 ----
    float4 ph[4];
    #pragma unroll
    for (int i = 0; i < 4; i++)
        ph[i] = *(const float4*)(hrow + srow * DN + sh16 + 4 * i);

    // ---- stage w; u_h [q][264] fp16 ----
    for (int i = tid; i < 3 * DN; i += 256) wsm[i] = wg[i];
    for (int idx = tid; idx < 64 * 64; idx += 256) {
        int q = idx >> 6, d4 = idx & 63;
        float4 v = *(const float4*)(ub + q * DN + d4 * 4);
        *(uint2*)((char*)u_h + q * 528 + d4 * 8) =
            make_uint2(pack_h2(v.x, v.y), pack_h2(v.z, v.w));
    }
    // ---- s_u[q] = u[q,:] . w2 (4 lanes per q) ----
    {
        int q = tid >> 2, sg = tid & 3;
        const float* up  = ub + q * DN + sg * 64;
        const float* w2p = wg + DN + sg * 64;
        float acc = 0.f;
        #pragma unroll 16
        for (int i = 0; i < 16; i++) {
            float4 a = *(const float4*)(up + 4 * i);
            float4 w = *(const float4*)(w2p + 4 * i);
            acc += a.x * w.x + a.y * w.y + a.z * w.z + a.w * w.w;
        }
        acc += __shfl_xor_sync(0xffffffffu, acc, 1, 4);
        acc += __shfl_xor_sync(0xffffffffu, acc, 2, 4);
        if (sg == 0) s_u[q] = acc;
    }
    __syncthreads();

    // ---- GEMM1: C1[128 j][64 q] = (h*w3).u^T, K=256, 8 chunks of 32, dbl-buf --
    float c1f[2][4][4];
    #pragma unroll
    for (int mt = 0; mt < 2; mt++)
        #pragma unroll
        for (int nt = 0; nt < 4; nt++)
            #pragma unroll
            for (int i = 0; i < 4; i++) c1f[mt][nt][i] = 0.f;

    float shp = 0.f;
    for (int c = 0; c < 8; c++) {
        __half* Ab = (__half*)(smc + OFF_AS + (c & 1) * 10240);
        {
            uint4 st0, st1;
            uint32_t* s0 = (uint32_t*)&st0;
            uint32_t* s1 = (uint32_t*)&st1;
            #pragma unroll
            for (int i = 0; i < 4; i++) {
                const int dd = c * 32 + sh16 + 4 * i;
                float4 x = ph[i];
                const float* w1p = wsm + dd;
                shp += x.x * w1p[0] + x.y * w1p[1] + x.z * w1p[2] + x.w * w1p[3];
                const float* w3p = wsm + 2 * DN + dd;
                uint32_t* dstp = (i < 2) ? (s0 + 2 * i) : (s1 + 2 * (i - 2));
                dstp[0] = pack_h2(x.x * w3p[0], x.y * w3p[1]);
                dstp[1] = pack_h2(x.z * w3p[2], x.w * w3p[3]);
            }
            *(uint4*)((char*)Ab + srow * 80 + sh16 * 2)      = st0;
            *(uint4*)((char*)Ab + srow * 80 + sh16 * 2 + 16) = st1;
        }
        __syncthreads();
        if (c < 7) {
            #pragma unroll
            for (int i = 0; i < 4; i++)
                ph[i] = *(const float4*)(hrow + srow * DN + (c + 1) * 32 + sh16 + 4 * i);
        }
        #pragma unroll
        for (int it = 0; it < 2; it++) {
            const int kb = it * 16;
            uint32_t af[2][4], bf[4][2];
            #pragma unroll
            for (int mt = 0; mt < 2; mt++) {
                const __half* ap = Ab + (wj * 32 + mt * 16 + g) * 40 + kb + 2 * t;
                af[mt][0] = *(const uint32_t*)ap;
                af[mt][1] = *(const uint32_t*)(ap + 8 * 40);
                af[mt][2] = *(const uint32_t*)(ap + 8);
                af[mt][3] = *(const uint32_t*)(ap + 8 * 40 + 8);
            }
            #pragma unroll
            for (int nt = 0; nt < 4; nt++) {
                const __half* bp = u_h + (wn * 32 + nt * 8 + g) * 264 + c * 32 + kb + 2 * t;
                bf[nt][0] = *(const uint32_t*)bp;
                bf[nt][1] = *(const uint32_t*)(bp + 8);
            }
            #pragma unroll
            for (int mt = 0; mt < 2; mt++)
                #pragma unroll
                for (int nt = 0; nt < 4; nt++)
                    MMA_F16(c1f[mt][nt], af[mt], bf[nt]);
        }
        // no trailing sync: next STS targets the other A buffer
    }

    // ---- s_h (written before the bar-6 rendezvous; read only by warp 0 after) --
    shp += __shfl_xor_sync(0xffffffffu, shp, 1, 2);
    if ((tid & 1) == 0) s_h[srow] = shp;

    // ---- fragment-resident softmax over q ----
    // Thread holds rows R(mt,ih) = wj*32 + mt*16 + ih*8 + g, cols q = wn*32+nt*8+2t(+1).
    {
        float vv[2][2][8];
        #pragma unroll
        for (int mt = 0; mt < 2; mt++)
            #pragma unroll
            for (int nt = 0; nt < 4; nt++) {
                const int q0 = wn * 32 + nt * 8 + 2 * t;
                const float su0 = s_u[q0], su1 = s_u[q0 + 1];
                vv[mt][0][2 * nt]     = c1f[mt][nt][0] + su0;
                vv[mt][0][2 * nt + 1] = c1f[mt][nt][1] + su1;
                vv[mt][1][2 * nt]     = c1f[mt][nt][2] + su0;
                vv[mt][1][2 * nt + 1] = c1f[mt][nt][3] + su1;
            }
        float mx[2][2], sm[2][2];
        #pragma unroll
        for (int mt = 0; mt < 2; mt++)
            #pragma unroll
            for (int ih = 0; ih < 2; ih++) {
                float m = vv[mt][ih][0];
                #pragma unroll
                for (int i = 1; i < 8; i++) m = fmaxf(m, vv[mt][ih][i]);
                m = fmaxf(m, __shfl_xor_sync(0xffffffffu, m, 1, 4));
                m = fmaxf(m, __shfl_xor_sync(0xffffffffu, m, 2, 4));
                mx[mt][ih] = m;
                if (t == 0) exch[wn * 128 + wj * 32 + mt * 16 + ih * 8 + g] = m;
            }
        NBAR(1 + wj, 64);
        #pragma unroll
        for (int mt = 0; mt < 2; mt++)
            #pragma unroll
            for (int ih = 0; ih < 2; ih++) {
                const int row = wj * 32 + mt * 16 + ih * 8 + g;
                mx[mt][ih] = fmaxf(mx[mt][ih], exch[(wn ^ 1) * 128 + row]);
                float s = 0.f;
                #pragma unroll
                for (int i = 0; i < 8; i++) {
                    vv[mt][ih][i] = __expf(vv[mt][ih][i] - mx[mt][ih]);
                    s += vv[mt][ih][i];
                }
                s += __shfl_xor_sync(0xffffffffu, s, 1, 4);
                s += __shfl_xor_sync(0xffffffffu, s, 2, 4);
                sm[mt][ih] = s;
            }
        NBAR(1 + wj, 64);   // all maxes read before exch reuse
        #pragma unroll
        for (int mt = 0; mt < 2; mt++)
            #pragma unroll
            for (int ih = 0; ih < 2; ih++)
                if (t == 0)
                    exch[wn * 128 + wj * 32 + mt * 16 + ih * 8 + g] = sm[mt][ih];
        NBAR(1 + wj, 64);
        #pragma unroll
        for (int mt = 0; mt < 2; mt++)
            #pragma unroll
            for (int ih = 0; ih < 2; ih++) {
                const int row = wj * 32 + mt * 16 + ih * 8 + g;
                const float inv = 1.f / (sm[mt][ih] + exch[(wn ^ 1) * 128 + row]);
                #pragma unroll
                for (int nt = 0; nt < 4; nt++) {
                    *(uint32_t*)((char*)P_h + row * 144 + (wn * 32 + nt * 8 + 2 * t) * 2)
                        = pack_h2(vv[mt][ih][2 * nt] * inv, vv[mt][ih][2 * nt + 1] * inv);
                }
                if (wn == 0 && t == 0) s_pm[row] = mx[mt][ih];
            }
    }
    NBAR(1 + wj, 64);   // P rows visible within the {wj, wj+4} pair

    // ---- rendezvous: warp 0 waits for all s_pm/s_h, computes p; others proceed --
    if (wid != 0) {
        NBARR(6, 256);
    } else {
        NBAR(6, 256);
        float v0 = s_pm[lane]      + s_h[lane];
        float v1 = s_pm[lane + 32] + s_h[lane + 32];
        float v2 = s_pm[lane + 64] + s_h[lane + 64];
        float v3 = s_pm[lane + 96] + s_h[lane + 96];
        float mxp = fmaxf(fmaxf(v0, v1), fmaxf(v2, v3));
        #pragma unroll
        for (int o = 16; o >= 1; o >>= 1) mxp = fmaxf(mxp, __shfl_xor_sync(0xffffffffu, mxp, o));
        float e0 = __expf(v0 - mxp), e1 = __expf(v1 - mxp);
        float e2 = __expf(v2 - mxp), e3 = __expf(v3 - mxp);
        float s = e0 + e1 + e2 + e3;
        #pragma unroll
        for (int o = 16; o >= 1; o >>= 1) s += __shfl_xor_sync(0xffffffffu, s, o);
        float inv = 1.f / s;
        p_s[lane] = e0 * inv; p_s[lane + 32] = e1 * inv;
        p_s[lane + 64] = e2 * inv; p_s[lane + 96] = e3 * inv;
    }

    // ---- GEMM2 (barrier-free): 2 d-slabs of 128; B via ldmatrix.trans on u_h --
    const uint32_t uh_b = smem_u32(u_h)
                        + (((lane >> 3) & 1) * 8 + (lane & 7)) * 528
                        + (lane >> 4) * 16;
    for (int s = 0; s < 2; s++) {
        float d2f[2][8][4];
        #pragma unroll
        for (int mt = 0; mt < 2; mt++)
            #pragma unroll
            for (int nt = 0; nt < 8; nt++)
                #pragma unroll
                for (int i = 0; i < 4; i++) d2f[mt][nt][i] = 0.f;

        #pragma unroll
        for (int it = 0; it < 4; it++) {
            const int kb = it * 16;
            uint32_t af[2][4];
            #pragma unroll
            for (int mt = 0; mt < 2; mt++) {
                const __half* ap = P_h + (wj * 32 + mt * 16 + g) * 72 + kb + 2 * t;
                af[mt][0] = *(const uint32_t*)ap;
                af[mt][1] = *(const uint32_t*)(ap + 8 * 72);
                af[mt][2] = *(const uint32_t*)(ap + 8);
                af[mt][3] = *(const uint32_t*)(ap + 8 * 72 + 8);
            }
            #pragma unroll
            for (int ntp = 0; ntp < 4; ntp++) {
                const uint32_t addr = uh_b + it * 16 * 528
                                    + (s * 128 + wn * 64 + ntp * 16) * 2;
                uint32_t r0, r1, r2, r3;
                LDMATRIX_X4_TRANS(r0, r1, r2, r3, addr);
                uint32_t bA[2] = {r0, r1}, bB[2] = {r2, r3};
                MMA_F16(d2f[0][2 * ntp],     af[0], bA);
                MMA_F16(d2f[1][2 * ntp],     af[1], bA);
                MMA_F16(d2f[0][2 * ntp + 1], af[0], bB);
                MMA_F16(d2f[1][2 * ntp + 1], af[1], bB);
            }
        }
        // direct epilogue: segments 0,1,2
        #pragma unroll
        for (int mt = 0; mt < 2; mt++) {
            const int R0 = wj * 32 + mt * 16 + g;
            const int R1 = R0 + 8;
            float* ob0 = out + outbase + (size_t)R0 * (4 * DN);
            float* ob1 = out + outbase + (size_t)R1 * (4 * DN);
            const float* h0 = hrow + R0 * DN;
            const float* h1 = hrow + R1 * DN;
            #pragma unroll
            for (int nt = 0; nt < 8; nt++) {
                const int d = s * 128 + wn * 64 + nt * 8 + 2 * t;
                float2 hv0 = *(const float2*)(h0 + d);
                float2 hv1 = *(const float2*)(h1 + d);
                float2 ua0 = make_float2(d2f[mt][nt][0], d2f[mt][nt][1]);
                float2 ua1 = make_float2(d2f[mt][nt][2], d2f[mt][nt][3]);
                *(float2*)(ob0 + d)          = hv0;
                *(float2*)(ob0 + DN + d)     = ua0;
                *(float2*)(ob0 + 2 * DN + d) = make_float2(hv0.x * ua0.x, hv0.y * ua0.y);
                *(float2*)(ob1 + d)          = hv1;
                *(float2*)(ob1 + DN + d)     = ua1;
                *(float2*)(ob1 + 2 * DN + d) = make_float2(hv1.x * ua1.x, hv1.y * ua1.y);
            }
        }
    }
    __syncthreads();   // p_s visible; A_s region free for part alias

    // ---- h_att = sum_j p_j h[j,:]; write segment 3 ----
    {
        const int jg = tid >> 6, dq = tid & 63;
        float4 acc = make_float4(0.f, 0.f, 0.f, 0.f);
        #pragma unroll 4
        for (int j = jg * 32; j < jg * 32 + 32; j++) {
            float4 hv = *(const float4*)(hrow + j * DN + dq * 4);
            float pj = p_s[j];
            acc.x += pj * hv.x; acc.y += pj * hv.y; acc.z += pj * hv.z; acc.w += pj * hv.w;
        }
        part[jg * 64 + dq] = acc;
        __syncthreads();
        if (tid < 64) {
            float4 sacc = part[tid];
            #pragma unroll
            for (int gg = 1; gg < 4; gg++) {
                float4 v = part[gg * 64 + tid];
                sacc.x += v.x; sacc.y += v.y; sacc.z += v.z; sacc.w += v.w;
            }
            part[tid] = sacc;
        }
        __syncthreads();
        const float4 ha = part[dq];
        #pragma unroll 4
        for (int j = jg * 32; j < jg * 32 + 32; j++) {
            float4 hv = *(const float4*)(hrow + j * DN + dq * 4);
            float4 o3;
            o3.x = hv.x * ha.x; o3.y = hv.y * ha.y; o3.z = hv.z * ha.z; o3.w = hv.w * ha.w;
            *(float4*)(out + outbase + (size_t)j * (4 * DN) + 3 * DN + dq * 4) = o3;
        }
    }
}

// ---------------------------------------------------------------------------
extern "C" void kernel_launch(void* const* d_in, const int* in_sizes, int n_in,
                              void* d_out, int out_size)
{
    (void)in_sizes; (void)n_in; (void)out_size;
    const float* h = (const float*)d_in[0];
    const float* u = (const float*)d_in[1];
    const float* w = (const float*)d_in[2];
    // d_in[3] (scalar bias b) cancels in both softmaxes -> unused.
    float* out = (float*)d_out;

    cudaFuncSetAttribute(attn_h16, cudaFuncAttributeMaxDynamicSharedMemorySize, SMEM_BYTES);
    attn_h16<<<BB * MM, 256, SMEM_BYTES>>>(h, u, w, out);
}